// round 5
// baseline (speedup 1.0000x reference)
#include <cuda_runtime.h>
#include <cuda_bf16.h>
#include <cstddef>

// ExponentialMovingAverage: out[b,t,c] = 0.1*x[b,t,c] + 0.9*out[b,t-1,c],
// out[b,0,c] = x[b,0,c].  Shape (16, 4096, 512) fp32.
//
// Time-parallel via truncated lookback: 0.9^128 ~ 1.4e-6, so each time
// segment reconstructs its incoming carry from a 128-step warm-up window
// with zero init. Segment 0 is exact. Error ~1e-6 relative, far below the
// 1e-3 harness threshold.

namespace {
constexpr int B = 16;
constexpr int T = 4096;
constexpr int C = 512;
constexpr int SEG_LEN = 512;
constexpr int NSEG = T / SEG_LEN;     // 8
constexpr int LOOKBACK = 128;         // 0.9^128 ~ 1.4e-6
constexpr int BLOCK_C = 128;          // threads per block (channels per block)
constexpr float ALPHA = 0.1f;
constexpr float BETA  = 0.9f;
}

__global__ __launch_bounds__(BLOCK_C, 8)
void ema_lookback_kernel(const float* __restrict__ x, float* __restrict__ out) {
    const int c   = blockIdx.x * BLOCK_C + threadIdx.x;   // channel
    const int seg = blockIdx.y;                           // time segment
    const int b   = blockIdx.z;                           // batch

    const size_t base = (size_t)b * T * C + (size_t)c;
    const float* __restrict__ xp = x   + base;
    float*       __restrict__ op = out + base;

    const int t0 = seg * SEG_LEN;
    float y;
    int tstart;

    if (seg == 0) {
        // Exact init: out[b,0,c] = x[b,0,c]
        y = xp[0];
        op[0] = y;
        tstart = 1;
    } else {
        // Warm-up: reconstruct carry from zero init over LOOKBACK steps.
        y = 0.0f;
        const int tl = t0 - LOOKBACK;
        #pragma unroll 16
        for (int k = 0; k < LOOKBACK; ++k) {
            const float xv = xp[(size_t)(tl + k) * C];
            y = fmaf(BETA, y, ALPHA * xv);   // dependent chain = 1 FFMA (4 cyc)
        }
        tstart = t0;
    }

    const int tend = t0 + SEG_LEN;
    #pragma unroll 16
    for (int t = tstart; t < tend; ++t) {
        const float xv = xp[(size_t)t * C];
        y = fmaf(BETA, y, ALPHA * xv);
        op[(size_t)t * C] = y;
    }
}

extern "C" void kernel_launch(void* const* d_in, const int* in_sizes, int n_in,
                              void* d_out, int out_size) {
    (void)in_sizes; (void)n_in; (void)out_size;
    const float* x = (const float*)d_in[0];
    float* out = (float*)d_out;

    dim3 grid(C / BLOCK_C, NSEG, B);   // (4, 8, 16) = 512 blocks
    dim3 block(BLOCK_C);               // 128 threads
    ema_lookback_kernel<<<grid, block>>>(x, out);
}